// round 2
// baseline (speedup 1.0000x reference)
#include <cuda_runtime.h>

// StructuralLoss: predictions (64, 8192, 60) fp32.
// Each of 64*8192 rows has 3 key blocks of 20 floats:
//   bid_l = v[2l] (l=0..4), ask_l = v[10+2l]
//   viol = sum_l max(ask_l - ask_{l+1},0) + sum_l max(bid_{l+1}-bid_l,0)
//        + max(bid0 - ask0, 0)
// output scalar = (1/64) * sum over all (row, key) units.
//
// Single fused kernel: grid-stride streaming reduction + threadfence/ticket
// last-block final reduce (deterministic; counter self-resets for graph replay).

#define NBLOCKS 1184
#define NTHREADS 256

__device__ float g_partials[NBLOCKS];
__device__ unsigned int g_ticket;   // zero-initialized; reset by last block each run

__device__ __forceinline__ float unit_viol(const float4* __restrict__ p)
{
    float4 a = p[0];
    float4 b = p[1];
    float4 c = p[2];
    float4 d = p[3];
    float4 e = p[4];
    float bid0 = a.x, bid1 = a.z, bid2 = b.x, bid3 = b.z, bid4 = c.x;
    float ask0 = c.z, ask1 = d.x, ask2 = d.z, ask3 = e.x, ask4 = e.z;

    float acc;
    acc  = fmaxf(ask0 - ask1, 0.0f);
    acc += fmaxf(ask1 - ask2, 0.0f);
    acc += fmaxf(ask2 - ask3, 0.0f);
    acc += fmaxf(ask3 - ask4, 0.0f);
    acc += fmaxf(bid1 - bid0, 0.0f);
    acc += fmaxf(bid2 - bid1, 0.0f);
    acc += fmaxf(bid3 - bid2, 0.0f);
    acc += fmaxf(bid4 - bid3, 0.0f);
    acc += fmaxf(bid0 - ask0, 0.0f);
    return acc;
}

__global__ __launch_bounds__(NTHREADS) void viol_kernel(
    const float* __restrict__ pred, int n_units, float* __restrict__ out)
{
    const int tid    = blockIdx.x * NTHREADS + threadIdx.x;
    const int stride = NBLOCKS * NTHREADS;

    float acc0 = 0.0f;
    float acc1 = 0.0f;

    // Two units per iteration -> 10 independent LDG.128 in flight per thread.
    int u = tid;
    for (; u + stride < n_units; u += 2 * stride) {
        const float4* p0 = reinterpret_cast<const float4*>(pred + (long long)u * 20);
        const float4* p1 = reinterpret_cast<const float4*>(pred + (long long)(u + stride) * 20);
        acc0 += unit_viol(p0);
        acc1 += unit_viol(p1);
    }
    if (u < n_units) {
        const float4* p0 = reinterpret_cast<const float4*>(pred + (long long)u * 20);
        acc0 += unit_viol(p0);
    }
    float acc = acc0 + acc1;

    // Deterministic block reduction: warp shuffle + shared
    __shared__ float s[NTHREADS / 32];
    #pragma unroll
    for (int o = 16; o > 0; o >>= 1)
        acc += __shfl_down_sync(0xffffffffu, acc, o);
    if ((threadIdx.x & 31) == 0) s[threadIdx.x >> 5] = acc;
    __syncthreads();

    __shared__ bool s_is_last;
    if (threadIdx.x < 32) {
        float v = (threadIdx.x < NTHREADS / 32) ? s[threadIdx.x] : 0.0f;
        #pragma unroll
        for (int o = 16; o > 0; o >>= 1)
            v += __shfl_down_sync(0xffffffffu, v, o);
        if (threadIdx.x == 0) {
            g_partials[blockIdx.x] = v;
            __threadfence();                       // make partial visible
            unsigned int t = atomicAdd(&g_ticket, 1u);
            s_is_last = (t == NBLOCKS - 1);
        }
    }
    __syncthreads();

    // Last block to arrive: all partials are globally visible. Final reduce.
    if (s_is_last) {
        float facc = 0.0f;
        for (int i = threadIdx.x; i < NBLOCKS; i += NTHREADS)
            facc += g_partials[i];
        #pragma unroll
        for (int o = 16; o > 0; o >>= 1)
            facc += __shfl_down_sync(0xffffffffu, facc, o);
        __shared__ float fs[NTHREADS / 32];
        if ((threadIdx.x & 31) == 0) fs[threadIdx.x >> 5] = facc;
        __syncthreads();
        if (threadIdx.x == 0) {
            float t = 0.0f;
            #pragma unroll
            for (int i = 0; i < NTHREADS / 32; i++) t += fs[i];
            out[0] = t * (1.0f / 64.0f);
            g_ticket = 0;                          // reset for next graph replay
        }
    }
}

extern "C" void kernel_launch(void* const* d_in, const int* in_sizes, int n_in,
                              void* d_out, int out_size)
{
    const float* pred = (const float*)d_in[0];
    float* out = (float*)d_out;
    int n_units = in_sizes[0] / 20;  // 64*8192*60 / 20 = 1,572,864

    viol_kernel<<<NBLOCKS, NTHREADS>>>(pred, n_units, out);
}